// round 1
// baseline (speedup 1.0000x reference)
#include <cuda_runtime.h>
#include <cuda_bf16.h>

// Problem constants (fixed by the dataset): B=2, N=8192, C=32.
// Key insight: nn_idx[0] == 0 always (self-distance 0, argmin takes first
// minimum), so the reference's N x N distance matrix is dead code and
// neighbor_feat = relu(features[b, 0, :]).
//
// Live math per batch b, row i:
//   f     = relu(features[b,i,:])
//   gamma = max_c( exp(f_c)/exp(f0_c) * f_c / max_c(f) )
//   out   = gamma / ||gamma||_2  (per batch)

#define DET_N 8192
#define DET_C 32
#define DET_MAXB 8

__device__ float g_gamma[DET_MAXB * DET_N];
__device__ float g_norm2[DET_MAXB];

__global__ void det_zero_kernel() {
    if (threadIdx.x < DET_MAXB) g_norm2[threadIdx.x] = 0.0f;
}

// One warp per row; lane == channel (C == 32).
// blockDim = 256 -> 8 rows per block. N % 8 == 0, so a block never
// straddles a batch boundary.
__global__ void det_gamma_kernel(const float* __restrict__ feat) {
    const int lane = threadIdx.x & 31;
    const int row  = (blockIdx.x * blockDim.x + threadIdx.x) >> 5;  // flat b*N + i
    const int b    = row >> 13;                                      // N = 8192

    // relu'd feature for this (row, channel)
    float v = fmaxf(feat[(row << 5) + lane], 0.0f);
    // relu'd row-0 feature of this batch (L2-broadcast load)
    float f0 = fmaxf(feat[((b << 13) << 5) + lane], 0.0f);

    // row max over channels (warp reduction)
    float m = v;
    #pragma unroll
    for (int o = 16; o; o >>= 1) m = fmaxf(m, __shfl_xor_sync(0xFFFFFFFFu, m, o));

    // alpha * beta, then gamma = warp max
    float s = (expf(v) / expf(f0)) * (v / m);
    #pragma unroll
    for (int o = 16; o; o >>= 1) s = fmaxf(s, __shfl_xor_sync(0xFFFFFFFFu, s, o));

    if (lane == 0) g_gamma[row] = s;

    // block-level partial of sum(gamma^2), one atomic per block
    __shared__ float sh[8];
    if (lane == 0) sh[threadIdx.x >> 5] = s * s;
    __syncthreads();
    if (threadIdx.x < 8) {
        float p = sh[threadIdx.x];
        #pragma unroll
        for (int o = 4; o; o >>= 1) p += __shfl_xor_sync(0xFFu, p, o);
        if (threadIdx.x == 0) atomicAdd(&g_norm2[b], p);
    }
}

__global__ void det_scale_kernel(float* __restrict__ out, int total) {
    int i = blockIdx.x * blockDim.x + threadIdx.x;
    if (i >= total) return;
    int b = i >> 13;
    out[i] = g_gamma[i] * rsqrtf(g_norm2[b]);
}

extern "C" void kernel_launch(void* const* d_in, const int* in_sizes, int n_in,
                              void* d_out, int out_size) {
    // inputs: [0] coords int32 [B,N,3] (unused), [1] features f32 [B,N,C], [2] len_batch
    const float* feat = (const float*)d_in[1];
    const int B = in_sizes[1] / (DET_N * DET_C);
    const int total_rows = B * DET_N;

    det_zero_kernel<<<1, 32>>>();

    // 8 rows per 256-thread block
    det_gamma_kernel<<<total_rows / 8, 256>>>(feat);

    det_scale_kernel<<<(total_rows + 255) / 256, 256>>>((float*)d_out, total_rows);
}

// round 2
// speedup vs baseline: 1.0117x; 1.0117x over previous
#include <cuda_runtime.h>
#include <cuda_bf16.h>

// Detection_23785528885376  (B=2, N=8192, C=32)
//
// Math collapse (see R0): nn_idx[0]==0 always, so neighbor_feat = relu(f[b,0,:]).
// Per row i of batch b:
//   f     = relu(features[b,i,:])
//   gamma = max_c( exp(f_c)/exp(f0_c) * f_c / max_c(f) )
//   out   = gamma / ||gamma||_2   (norm per batch)
//
// R1 lesson: we are graph-node-overhead bound (~3.7us/node). This version is a
// SINGLE kernel: per-block partial norms into distinct slots (no atomics, no
// zero-init node), a replay-safe ticket grid-barrier, then scale from registers.

#define DET_N  8192
#define DET_C  32
#define GRID   512
#define BLOCK  256
#define ROWS_PER_BLOCK 32   // (B*N)/GRID = 16384/512
#define ITERS  4            // 8 warps * 4 iters = 32 rows

__device__ unsigned int g_ctr;          // monotonic ticket counter (never reset)
__device__ float g_partial[GRID];       // per-block sum(gamma^2)

__global__ void __launch_bounds__(BLOCK, 8)
det_fused_kernel(const float* __restrict__ feat, float* __restrict__ out,
                 int nblocks_per_batch) {
    const int lane = threadIdx.x & 31;
    const int warp = threadIdx.x >> 5;
    const int b    = blockIdx.x / nblocks_per_batch;
    const int row_base = blockIdx.x * ROWS_PER_BLOCK;

    // relu'd row-0 feature of this batch (L2-broadcast across blocks)
    const float f0  = fmaxf(__ldg(&feat[(b * DET_N) * DET_C + lane]), 0.0f);
    const float ef0 = expf(f0);

    // ---- Phase 1: gamma for 4 rows per warp, kept in registers ----
    float s_arr[ITERS];
    float ssum = 0.0f;                  // sum of gamma^2 over this warp's rows
    #pragma unroll
    for (int j = 0; j < ITERS; j++) {
        const int row = row_base + j * 8 + warp;
        float v = fmaxf(feat[row * DET_C + lane], 0.0f);
        float m = v;
        #pragma unroll
        for (int o = 16; o; o >>= 1) m = fmaxf(m, __shfl_xor_sync(0xFFFFFFFFu, m, o));
        float s = (expf(v) / ef0) * (v / m);
        #pragma unroll
        for (int o = 16; o; o >>= 1) s = fmaxf(s, __shfl_xor_sync(0xFFFFFFFFu, s, o));
        s_arr[j] = s;                   // every lane holds gamma(row)
        ssum += s * s;
    }

    // block partial: 8 warp sums -> one float (fixed order, deterministic)
    __shared__ float sh[8];
    __shared__ float sh_inv;
    if (lane == 0) sh[warp] = ssum;
    __syncthreads();
    if (threadIdx.x == 0) {
        float p = sh[0];
        #pragma unroll
        for (int w = 1; w < 8; w++) p += sh[w];
        g_partial[blockIdx.x] = p;
        __threadfence();                               // publish partial
        // ---- replay-safe grid barrier (all GRID blocks are one wave) ----
        unsigned ticket = atomicAdd(&g_ctr, 1u);
        unsigned target = (ticket / gridDim.x + 1u) * gridDim.x;
        while (*((volatile unsigned int*)&g_ctr) < target) { }
        __threadfence();                               // acquire partials
    }
    __syncthreads();

    // ---- Phase 2: per-batch norm from partials (volatile, fixed order) ----
    float p = 0.0f;
    for (int i = threadIdx.x; i < nblocks_per_batch; i += BLOCK)
        p += *((volatile float*)&g_partial[b * nblocks_per_batch + i]);
    #pragma unroll
    for (int o = 16; o; o >>= 1) p += __shfl_xor_sync(0xFFFFFFFFu, p, o);
    if (lane == 0) sh[warp] = p;
    __syncthreads();
    if (threadIdx.x == 0) {
        float t = sh[0];
        #pragma unroll
        for (int w = 1; w < 8; w++) t += sh[w];
        sh_inv = rsqrtf(t);
    }
    __syncthreads();
    const float inv = sh_inv;

    // ---- write gamma * inv (from registers) ----
    if (lane == 0) {
        #pragma unroll
        for (int j = 0; j < ITERS; j++)
            out[row_base + j * 8 + warp] = s_arr[j] * inv;
    }
}

extern "C" void kernel_launch(void* const* d_in, const int* in_sizes, int n_in,
                              void* d_out, int out_size) {
    // inputs: [0] coords int32 (unused), [1] features f32 [B,N,C], [2] len_batch
    const float* feat = (const float*)d_in[1];
    const int B = in_sizes[1] / (DET_N * DET_C);
    const int total_rows = B * DET_N;
    const int grid = total_rows / ROWS_PER_BLOCK;       // 512 for B=2

    det_fused_kernel<<<grid, BLOCK>>>(feat, (float*)d_out, grid / B);
}

// round 3
// speedup vs baseline: 1.2437x; 1.2294x over previous
#include <cuda_runtime.h>
#include <cuda_bf16.h>

// Detection_23785528885376  (B=2, N=8192, C=32)
//
// Math collapse (R0): nn_idx[0]==0 always -> neighbor_feat = relu(f[b,0,:]).
// Per row: gamma = max_c( exp(f_c - f0_c) * f_c / max_c f );  out = gamma/||gamma||_2 per batch.
//
// R2 lesson: 512-way ticket barrier (atomics serialized on one L2 address +
// 512 volatile pollers) cost ~6us. This version: 64 blocks x 512 threads,
// nanosleep-backoff spin, shared-staged gamma, coalesced output.

#define DET_N  8192
#define DET_C  32
#define BPB    32              // blocks per batch
#define BLOCK  512             // 16 warps
#define ROWS_PER_BLOCK 256     // DET_N / BPB
#define ROWS_PER_WARP  16      // ROWS_PER_BLOCK / 16 warps
#define DET_MAXB 8

__device__ unsigned int g_ctr;                 // monotonic ticket (replay-safe, never reset)
__device__ float g_partial[DET_MAXB * BPB];    // per-block sum(gamma^2)

__global__ void __launch_bounds__(BLOCK)
det_fused_kernel(const float* __restrict__ feat, float* __restrict__ out) {
    const int lane = threadIdx.x & 31;
    const int warp = threadIdx.x >> 5;                  // 0..15
    const int b    = blockIdx.x >> 5;                   // BPB = 32
    const int block_row0 = blockIdx.x * ROWS_PER_BLOCK;

    __shared__ float sh_gamma[ROWS_PER_BLOCK];
    __shared__ float sh_red[16];
    __shared__ float sh_inv;

    // relu'd row-0 feature of this batch (L2-broadcast across blocks)
    const float f0 = fmaxf(__ldg(&feat[b * DET_N * DET_C + lane]), 0.0f);

    // ---- Phase 1: 16 rows per warp; preload for MLP, then reduce ----
    const int warp_row0 = block_row0 + warp * ROWS_PER_WARP;
    float v[ROWS_PER_WARP];
    #pragma unroll
    for (int j = 0; j < ROWS_PER_WARP; j++)
        v[j] = fmaxf(feat[(warp_row0 + j) * DET_C + lane], 0.0f);

    #pragma unroll
    for (int j = 0; j < ROWS_PER_WARP; j++) {
        float m = v[j];
        #pragma unroll
        for (int o = 16; o; o >>= 1) m = fmaxf(m, __shfl_xor_sync(0xFFFFFFFFu, m, o));
        float s = __expf(v[j] - f0) * __fdividef(v[j], m);   // alpha*beta
        #pragma unroll
        for (int o = 16; o; o >>= 1) s = fmaxf(s, __shfl_xor_sync(0xFFFFFFFFu, s, o));
        if (lane == 0) sh_gamma[warp * ROWS_PER_WARP + j] = s;
    }
    __syncthreads();

    // ---- block partial of sum(gamma^2), fixed order (deterministic) ----
    float p = (threadIdx.x < ROWS_PER_BLOCK)
                  ? sh_gamma[threadIdx.x] * sh_gamma[threadIdx.x] : 0.0f;
    #pragma unroll
    for (int o = 16; o; o >>= 1) p += __shfl_xor_sync(0xFFFFFFFFu, p, o);
    if (lane == 0) sh_red[warp] = p;
    __syncthreads();

    // ---- grid barrier: 64 atomics total, nanosleep-backoff poll ----
    if (threadIdx.x == 0) {
        float q = sh_red[0];
        #pragma unroll
        for (int w = 1; w < 16; w++) q += sh_red[w];
        g_partial[blockIdx.x] = q;
        __threadfence();                                   // publish partial
        unsigned ticket = atomicAdd(&g_ctr, 1u);
        unsigned target = (ticket / gridDim.x + 1u) * gridDim.x;
        while (*((volatile unsigned int*)&g_ctr) < target)
            __nanosleep(64);
        __threadfence();                                   // acquire partials
    }
    __syncthreads();

    // ---- Phase 2: per-batch norm (warp 0), broadcast, coalesced scale ----
    if (warp == 0) {
        float q = *((volatile float*)&g_partial[b * BPB + lane]);   // BPB == 32
        #pragma unroll
        for (int o = 16; o; o >>= 1) q += __shfl_xor_sync(0xFFFFFFFFu, q, o);
        if (lane == 0) sh_inv = rsqrtf(q);
    }
    __syncthreads();

    if (threadIdx.x < ROWS_PER_BLOCK)
        out[block_row0 + threadIdx.x] = sh_gamma[threadIdx.x] * sh_inv;
}

extern "C" void kernel_launch(void* const* d_in, const int* in_sizes, int n_in,
                              void* d_out, int out_size) {
    // inputs: [0] coords int32 (unused), [1] features f32 [B,N,C], [2] len_batch
    const float* feat = (const float*)d_in[1];
    const int B = in_sizes[1] / (DET_N * DET_C);
    det_fused_kernel<<<B * BPB, BLOCK>>>(feat, (float*)d_out);
}

// round 4
// speedup vs baseline: 1.5354x; 1.2345x over previous
#include <cuda_runtime.h>
#include <cuda_bf16.h>

// Detection_23785528885376  (B=2, N=8192, C=32)
//
// Math collapse (R0): nn_idx[0]==0 always -> neighbor_feat = relu(f[b,0,:]).
// Per row: gamma = max_c( exp(f_c - f0_c) * f_c / max_c f ); out = gamma/||gamma||_2 per batch.
//
// R3 lesson: single-address ticket barrier serialized 64 atomics (~1700cyc) and
// we likely run at idle clocks, so every critical-path cycle is ~5x wall cost.
// This version: per-block (seq|partial) packed 64-bit slots -> parallel arrival,
// poll==data-read; float4 loads; 8-lane segment reductions (3 shfls).

#define DET_N  8192
#define DET_C  32
#define BPB    32              // blocks per batch
#define BLOCK  512             // 16 warps
#define ROWS_PER_BLOCK 256     // DET_N / BPB
#define ROWS_PER_WARP  16
#define MAX_SLOTS 256

__device__ unsigned int       g_seq [MAX_SLOTS];   // per-block replay counter (never reset)
__device__ unsigned long long g_slot[MAX_SLOTS];   // packed (seq<<32 | float bits)

__global__ void __launch_bounds__(BLOCK)
det_fused_kernel(const float* __restrict__ feat, float* __restrict__ out) {
    const int lane = threadIdx.x & 31;
    const int warp = threadIdx.x >> 5;        // 0..15
    const int seg  = lane >> 3;               // 0..3 : row within a float4-load group
    const int sid  = lane & 7;                // 0..7 : 8 lanes per row, 4 channels each
    const int b    = blockIdx.x >> 5;         // BPB == 32
    const int block_row0 = blockIdx.x * ROWS_PER_BLOCK;
    const int warp_row0  = block_row0 + warp * ROWS_PER_WARP;

    __shared__ float sh_gamma[ROWS_PER_BLOCK];
    __shared__ float sh_red[16];
    __shared__ float sh_inv;
    __shared__ unsigned int sh_seq;

    const float4* __restrict__ feat4 = (const float4*)feat;

    // relu'd row-0 feature of this batch; this lane's 4 channels
    float4 f0 = __ldg(&feat4[b * DET_N * (DET_C / 4) + sid]);
    f0.x = fmaxf(f0.x, 0.f); f0.y = fmaxf(f0.y, 0.f);
    f0.z = fmaxf(f0.z, 0.f); f0.w = fmaxf(f0.w, 0.f);

    // ---- Phase 1: preload 4x float4 (16 rows / warp, 4 rows per LDG.128) ----
    float4 t[4];
    #pragma unroll
    for (int j = 0; j < 4; j++)
        t[j] = feat4[(warp_row0 + j * 4) * (DET_C / 4) + lane];

    #pragma unroll
    for (int j = 0; j < 4; j++) {
        float v0 = fmaxf(t[j].x, 0.f), v1 = fmaxf(t[j].y, 0.f);
        float v2 = fmaxf(t[j].z, 0.f), v3 = fmaxf(t[j].w, 0.f);
        // row max over 32 channels: 4 local + 3 shfls within the 8-lane segment
        float m = fmaxf(fmaxf(v0, v1), fmaxf(v2, v3));
        #pragma unroll
        for (int o = 1; o < 8; o <<= 1) m = fmaxf(m, __shfl_xor_sync(0xFFFFFFFFu, m, o));
        float rm = __fdividef(1.0f, m);
        // gamma = max_c exp(v-f0) * v / m
        float s0 = __expf(v0 - f0.x) * v0 * rm;
        float s1 = __expf(v1 - f0.y) * v1 * rm;
        float s2 = __expf(v2 - f0.z) * v2 * rm;
        float s3 = __expf(v3 - f0.w) * v3 * rm;
        float s = fmaxf(fmaxf(s0, s1), fmaxf(s2, s3));
        #pragma unroll
        for (int o = 1; o < 8; o <<= 1) s = fmaxf(s, __shfl_xor_sync(0xFFFFFFFFu, s, o));
        if (sid == 0) sh_gamma[warp * ROWS_PER_WARP + j * 4 + seg] = s;
    }
    __syncthreads();

    // ---- block partial of sum(gamma^2), fixed order (deterministic) ----
    float p = (threadIdx.x < ROWS_PER_BLOCK)
                  ? sh_gamma[threadIdx.x] * sh_gamma[threadIdx.x] : 0.0f;
    #pragma unroll
    for (int o = 16; o; o >>= 1) p += __shfl_xor_sync(0xFFFFFFFFu, p, o);
    if (lane == 0) sh_red[warp] = p;
    __syncthreads();

    // ---- publish (seq | partial) to our own slot: parallel arrival ----
    if (threadIdx.x == 0) {
        float q = sh_red[0];
        #pragma unroll
        for (int w = 1; w < 16; w++) q += sh_red[w];
        unsigned my = atomicAdd(&g_seq[blockIdx.x], 1u) + 1u;     // uncontended
        unsigned long long pk =
            ((unsigned long long)my << 32) | (unsigned long long)__float_as_uint(q);
        atomicExch(&g_slot[blockIdx.x], pk);                      // flag+data, one word
        sh_seq = my;
    }
    __syncthreads();

    // ---- Phase 2: warp 0 polls the 32 batch-peer slots (poll == data read) ----
    if (warp == 0) {
        const unsigned target = sh_seq;
        volatile unsigned long long* slot =
            (volatile unsigned long long*)&g_slot[b * BPB + lane];
        unsigned long long v;
        bool ready;
        do {
            v = *slot;
            ready = (unsigned)(v >> 32) >= target;
        } while (!__all_sync(0xFFFFFFFFu, ready));
        float q = __uint_as_float((unsigned)(v & 0xFFFFFFFFu));
        #pragma unroll
        for (int o = 16; o; o >>= 1) q += __shfl_xor_sync(0xFFFFFFFFu, q, o);
        if (lane == 0) sh_inv = rsqrtf(q);
    }
    __syncthreads();

    if (threadIdx.x < ROWS_PER_BLOCK)
        out[block_row0 + threadIdx.x] = sh_gamma[threadIdx.x] * sh_inv;
}

extern "C" void kernel_launch(void* const* d_in, const int* in_sizes, int n_in,
                              void* d_out, int out_size) {
    // inputs: [0] coords int32 (unused), [1] features f32 [B,N,C], [2] len_batch
    const float* feat = (const float*)d_in[1];
    const int B = in_sizes[1] / (DET_N * DET_C);
    det_fused_kernel<<<B * BPB, BLOCK>>>(feat, (float*)d_out);
}